// round 12
// baseline (speedup 1.0000x reference)
#include <cuda_runtime.h>
#include <cuda_bf16.h>
#include <math.h>
#include <stdint.h>

#define NTOK 1024
#define CDIM 64
#define BATCH 2
#define SS (NTOK*NTOK)
#define KSEL (SS/6)   /* 174762 */

// ---------------- device scratch (no allocations allowed) ----------------
__device__ __nv_bfloat16 g_e0[BATCH*SS], g_e1[BATCH*SS], g_e2[BATCH*SS];
__device__ __nv_bfloat16 g_h0[BATCH*SS], g_h1[BATCH*SS], g_h2[BATCH*SS];
__device__ __nv_bfloat16 g_r0[BATCH*SS], g_r1[BATCH*SS], g_r2[BATCH*SS];
__device__ __nv_bfloat16 g_a0[BATCH*SS], g_a1[BATCH*SS], g_a2[BATCH*SS];
__device__ float g_L[BATCH*SS];
__device__ float g_W[BATCH*SS];
__device__ unsigned g_h12[BATCH][4096];
__device__ unsigned long long g_cand[BATCH][SS];
struct Sel3 { unsigned P12, kneed, T, idxT, ncand; };
__device__ Sel3 g_s3[BATCH];

__device__ __forceinline__ unsigned fkey(float f) {
    unsigned u = __float_as_uint(f);
    return (u & 0x80000000u) ? ~u : (u | 0x80000000u);
}

__device__ __forceinline__ void split3(float v, __nv_bfloat16* p0,
                                       __nv_bfloat16* p1, __nv_bfloat16* p2) {
    __nv_bfloat16 b0 = __float2bfloat16(v);
    float r = v - __bfloat162float(b0);
    __nv_bfloat16 b1 = __float2bfloat16(r);
    float r2 = r - __bfloat162float(b1);
    *p0 = b0; *p1 = b1; *p2 = __float2bfloat16(r2);
}

__device__ __forceinline__ uint32_t s2u(const void* p) {
    uint32_t a;
    asm("{ .reg .u64 t; cvta.to.shared.u64 t, %1; cvt.u32.u64 %0, t; }" : "=r"(a) : "l"(p));
    return a;
}

// ---------------- fused pairwise (upper triangle) -> bf16 splits ----------------
__global__ __launch_bounds__(256) void pairwise(const float* __restrict__ x) {
    __shared__ float xi[32][CDIM + 1];
    __shared__ float xj[32][CDIM + 1];
    __shared__ float smi[32], ssi[32], smj[32], ssj[32];
    __shared__ __nv_bfloat16 tb[9][32][36];
    int b = blockIdx.z;
    int t = blockIdx.x;
    int tid = threadIdx.x;

    if (b == 0 && t < 32) {
        int gid = t * 256 + tid;
        ((unsigned*)g_h12)[gid] = 0;
        if (gid < BATCH) g_s3[gid].ncand = 0;
    }

    int bi = (int)((65.0f - sqrtf(4225.0f - 8.0f * (float)t)) * 0.5f);
    while (32*bi - bi*(bi-1)/2 > t) bi--;
    while (32*(bi+1) - (bi+1)*bi/2 <= t) bi++;
    int bj = bi + (t - (32*bi - bi*(bi-1)/2));
    int i0 = bi * 32, j0 = bj * 32;

    const float* xb = x + (size_t)b * NTOK * CDIM;
    for (int l = tid; l < 32 * CDIM; l += 256) {
        int r = l >> 6, c = l & 63;
        xi[r][c] = xb[(size_t)(i0 + r) * CDIM + c];
        xj[r][c] = xb[(size_t)(j0 + r) * CDIM + c];
    }
    __syncthreads();

    {
        int warp = tid >> 5, lane = tid & 31;
        #pragma unroll
        for (int rr = 0; rr < 4; rr++) {
            int row = warp * 4 + rr;
            {
                float v0 = xi[row][lane], v1 = xi[row][lane + 32];
                float s = v0 + v1;
                #pragma unroll
                for (int o = 16; o; o >>= 1) s += __shfl_xor_sync(0xFFFFFFFFu, s, o);
                float mean = s * (1.0f / CDIM);
                float d0 = v0 - mean, d1 = v1 - mean;
                float ss = d0 * d0 + d1 * d1;
                #pragma unroll
                for (int o = 16; o; o >>= 1) ss += __shfl_xor_sync(0xFFFFFFFFu, ss, o);
                if (lane == 0) { smi[row] = mean; ssi[row] = sqrtf(ss); }
            }
            {
                float v0 = xj[row][lane], v1 = xj[row][lane + 32];
                float s = v0 + v1;
                #pragma unroll
                for (int o = 16; o; o >>= 1) s += __shfl_xor_sync(0xFFFFFFFFu, s, o);
                float mean = s * (1.0f / CDIM);
                float d0 = v0 - mean, d1 = v1 - mean;
                float ss = d0 * d0 + d1 * d1;
                #pragma unroll
                for (int o = 16; o; o >>= 1) ss += __shfl_xor_sync(0xFFFFFFFFu, ss, o);
                if (lane == 0) { smj[row] = mean; ssj[row] = sqrtf(ss); }
            }
        }
    }
    __syncthreads();

    int tx = tid & 15, ty = tid >> 4;
    int r0 = ty * 2, r1 = ty * 2 + 1;
    int c0 = tx, c1 = tx + 16;

    float ssq[2][2] = {{0,0},{0,0}};
    float mx[2][2]  = {{0,0},{0,0}};
    float dt[2][2]  = {{0,0},{0,0}};
    float mi0 = smi[r0], mi1 = smi[r1], mj0 = smj[c0], mj1 = smj[c1];

    #pragma unroll 16
    for (int c = 0; c < CDIM; c++) {
        float a0 = xi[r0][c], a1 = xi[r1][c];
        float b0 = xj[c0][c], b1 = xj[c1][c];
        float ac0 = a0 - mi0, ac1 = a1 - mi1;
        float bc0 = b0 - mj0, bc1 = b1 - mj1;
        float d;
        d = a0 - b0; ssq[0][0] = fmaf(d,d,ssq[0][0]); mx[0][0] = fmaxf(mx[0][0], fabsf(d)); dt[0][0] = fmaf(ac0,bc0,dt[0][0]);
        d = a0 - b1; ssq[0][1] = fmaf(d,d,ssq[0][1]); mx[0][1] = fmaxf(mx[0][1], fabsf(d)); dt[0][1] = fmaf(ac0,bc1,dt[0][1]);
        d = a1 - b0; ssq[1][0] = fmaf(d,d,ssq[1][0]); mx[1][0] = fmaxf(mx[1][0], fabsf(d)); dt[1][0] = fmaf(ac1,bc0,dt[1][0]);
        d = a1 - b1; ssq[1][1] = fmaf(d,d,ssq[1][1]); mx[1][1] = fmaxf(mx[1][1], fabsf(d)); dt[1][1] = fmaf(ac1,bc1,dt[1][1]);
    }

    size_t boff = (size_t)b * SS;
    __nv_bfloat16* Gm[9] = { g_e0+boff, g_e1+boff, g_e2+boff,
                             g_h0+boff, g_h1+boff, g_h2+boff,
                             g_r0+boff, g_r1+boff, g_r2+boff };
    __nv_bfloat16 sv[9][2][2];
    #pragma unroll
    for (int p = 0; p < 2; p++) {
        float si = ssi[r0 + p];
        #pragma unroll
        for (int q = 0; q < 2; q++) {
            split3(sqrtf(ssq[p][q]), &sv[0][p][q], &sv[1][p][q], &sv[2][p][q]);
            split3(mx[p][q],         &sv[3][p][q], &sv[4][p][q], &sv[5][p][q]);
            float cr = dt[p][q] / (si * ssj[(q==0)?c0:c1]);
            cr = fminf(fmaxf(cr, -1.0f), 1.0f);
            split3(cr, &sv[6][p][q], &sv[7][p][q], &sv[8][p][q]);
        }
    }

    #pragma unroll
    for (int m = 0; m < 9; m++) {
        #pragma unroll
        for (int p = 0; p < 2; p++) {
            #pragma unroll
            for (int q = 0; q < 2; q++) {
                int I = i0 + r0 + p;
                int J = j0 + ((q == 0) ? c0 : c1);
                Gm[m][(size_t)I * NTOK + J] = sv[m][p][q];
            }
        }
    }

    if (bi != bj) {
        #pragma unroll
        for (int m = 0; m < 9; m++) {
            tb[m][c0][r0] = sv[m][0][0];
            tb[m][c0][r1] = sv[m][1][0];
            tb[m][c1][r0] = sv[m][0][1];
            tb[m][c1][r1] = sv[m][1][1];
        }
        __syncthreads();
        int wr = tid >> 3, wc = (tid & 7) * 4;
        #pragma unroll
        for (int m = 0; m < 9; m++) {
            uint2 v = *(const uint2*)&tb[m][wr][wc];
            *(uint2*)(Gm[m] + (size_t)(j0 + wr) * NTOK + i0 + wc) = v;
        }
    }
}

// ---------------- bf16x6 GEMM via mma.sync (HMMA), 512 threads: D = A * B^T ----------------
#define KC 32
#define ROWB 80
#define TILEB (128*ROWB)
#define STAGEB (6*TILEB)
#define GSMEM (2*STAGEB)

#define LDSM4(r, a) \
    asm volatile("ldmatrix.sync.aligned.m8n8.x4.shared.b16 {%0,%1,%2,%3}, [%4];" \
        : "=r"((r)[0]), "=r"((r)[1]), "=r"((r)[2]), "=r"((r)[3]) : "r"(a))

#define MMA16816(d, a, b0r, b1r) \
    asm volatile("mma.sync.aligned.m16n8k16.row.col.f32.bf16.bf16.f32 " \
        "{%0,%1,%2,%3}, {%4,%5,%6,%7}, {%8,%9}, {%0,%1,%2,%3};" \
        : "+f"((d)[0]), "+f"((d)[1]), "+f"((d)[2]), "+f"((d)[3]) \
        : "r"((a)[0]), "r"((a)[1]), "r"((a)[2]), "r"((a)[3]), "r"(b0r), "r"(b1r))

__global__ __launch_bounds__(512, 1) void gemm_mma(int which) {
    extern __shared__ __align__(128) char dsm[];
    uint32_t sb = s2u(dsm);
    int tid = threadIdx.x, lane = tid & 31, wid = tid >> 5;
    int wm = wid >> 2, wn = wid & 3;   // warp grid 4x4, warp tile 32x32
    size_t boff = (size_t)blockIdx.z * SS;
    const __nv_bfloat16* mats[6];
    if (which == 0) {
        mats[0]=g_e0+boff; mats[1]=g_e1+boff; mats[2]=g_e2+boff;
        mats[3]=g_h0+boff; mats[4]=g_h1+boff; mats[5]=g_h2+boff;
    } else {
        mats[0]=g_a0+boff; mats[1]=g_a1+boff; mats[2]=g_a2+boff;
        mats[3]=g_r0+boff; mats[4]=g_r1+boff; mats[5]=g_r2+boff;
    }
    float* C = (which == 0 ? g_L : g_W) + boff;
    int rowBase = blockIdx.y * 128, colBase = blockIdx.x * 128;

    float acc[2][4][4];
    #pragma unroll
    for (int i = 0; i < 2; i++)
        #pragma unroll
        for (int j = 0; j < 4; j++)
            #pragma unroll
            for (int k = 0; k < 4; k++) acc[i][j][k] = 0.0f;

    unsigned aRowOff = (unsigned)(wm*32 + (lane & 15)) * ROWB + ((lane >> 4) << 4);
    unsigned bRowOff = (unsigned)(wn*32 + (lane & 7) + ((lane >> 4) << 3)) * ROWB
                     + (((lane >> 3) & 1) << 4);

// 512 threads: thread tid loads 16B chunk tid of tile i (512 chunks per tile)
#define LOADSTAGE(st, k0) do { \
    unsigned _so = sb + (unsigned)(st)*STAGEB; \
    int _row = tid >> 2, _c8 = tid & 3; \
    _Pragma("unroll") \
    for (int i = 0; i < 6; i++) { \
        int rb = (i < 3) ? rowBase : colBase; \
        const __nv_bfloat16* gp = mats[i] + (size_t)(rb + _row) * NTOK + (k0) + _c8*8; \
        unsigned sa = _so + i*TILEB + _row*ROWB + _c8*16; \
        asm volatile("cp.async.cg.shared.global [%0], [%1], 16;" :: "r"(sa), "l"(gp)); \
    } \
    asm volatile("cp.async.commit_group;"); \
} while(0)

    LOADSTAGE(0, 0);

    const int pa[6] = {0,0,1,0,1,2}, pb[6] = {0,1,0,2,1,0};

    for (int t = 0; t < 32; t++) {
        if (t < 31) {
            LOADSTAGE((t + 1) & 1, (t + 1) * KC);
            asm volatile("cp.async.wait_group 1;");
        } else {
            asm volatile("cp.async.wait_group 0;");
        }
        __syncthreads();
        unsigned stoff = sb + (unsigned)(t & 1) * STAGEB;
        #pragma unroll
        for (int kf = 0; kf < 2; kf++) {
            uint32_t af[3][2][4];
            uint32_t bf[3][2][4];
            #pragma unroll
            for (int s = 0; s < 3; s++) {
                #pragma unroll
                for (int mf = 0; mf < 2; mf++)
                    LDSM4(af[s][mf], stoff + s*TILEB + aRowOff + mf*(16*ROWB) + kf*32);
                #pragma unroll
                for (int np = 0; np < 2; np++)
                    LDSM4(bf[s][np], stoff + (3+s)*TILEB + bRowOff + np*(16*ROWB) + kf*32);
            }
            #pragma unroll
            for (int p = 0; p < 6; p++) {
                int sa = pa[p], sbp = pb[p];
                #pragma unroll
                for (int mf = 0; mf < 2; mf++) {
                    MMA16816(acc[mf][0], af[sa][mf], bf[sbp][0][0], bf[sbp][0][1]);
                    MMA16816(acc[mf][1], af[sa][mf], bf[sbp][0][2], bf[sbp][0][3]);
                    MMA16816(acc[mf][2], af[sa][mf], bf[sbp][1][0], bf[sbp][1][1]);
                    MMA16816(acc[mf][3], af[sa][mf], bf[sbp][1][2], bf[sbp][1][3]);
                }
            }
        }
        __syncthreads();
    }

    int r0 = rowBase + wm * 32 + (lane >> 2);
    int c0 = colBase + wn * 32 + (lane & 3) * 2;
    #pragma unroll
    for (int mf = 0; mf < 2; mf++) {
        #pragma unroll
        for (int nb = 0; nb < 4; nb++) {
            float* base = C + (size_t)(r0 + mf * 16) * NTOK + c0 + nb * 8;
            *(float2*)base = make_float2(acc[mf][nb][0], acc[mf][nb][1]);
            *(float2*)(base + 8 * NTOK) = make_float2(acc[mf][nb][2], acc[mf][nb][3]);
        }
    }

    // ---- fused selection histogram (gemm2 only): 32 acc values x 512 threads ----
    if (which == 1) {
        unsigned* hist = (unsigned*)dsm;
        __syncthreads();
        for (int i = tid; i < 4096; i += 512) hist[i] = 0;
        __syncthreads();
        #pragma unroll
        for (int mf = 0; mf < 2; mf++)
            #pragma unroll
            for (int nb = 0; nb < 4; nb++)
                #pragma unroll
                for (int k = 0; k < 4; k++)
                    atomicAdd(&hist[fkey(acc[mf][nb][k]) >> 20], 1u);
        __syncthreads();
        int b = blockIdx.z;
        for (int i = tid; i < 4096; i += 512)
            if (hist[i]) atomicAdd(&g_h12[b][i], hist[i]);
    }
#undef LOADSTAGE
}

// ---------------- row softmax of 0.125*L -> attn bf16 splits ----------------
__global__ void softmax_rows() {
    int b = blockIdx.y, row = blockIdx.x;
    size_t base = (size_t)b * SS + (size_t)row * NTOK;
    float* L = g_L + base;
    int tid = threadIdx.x;  // 256
    float v[4];
    #pragma unroll
    for (int i = 0; i < 4; i++) v[i] = L[tid + i * 256] * 0.125f;
    float m = fmaxf(fmaxf(v[0], v[1]), fmaxf(v[2], v[3]));
    __shared__ float red[256];
    red[tid] = m; __syncthreads();
    for (int s = 128; s; s >>= 1) { if (tid < s) red[tid] = fmaxf(red[tid], red[tid + s]); __syncthreads(); }
    m = red[0]; __syncthreads();
    float e[4], sm = 0.0f;
    #pragma unroll
    for (int i = 0; i < 4; i++) { e[i] = expf(v[i] - m); sm += e[i]; }
    red[tid] = sm; __syncthreads();
    for (int s = 128; s; s >>= 1) { if (tid < s) red[tid] += red[tid + s]; __syncthreads(); }
    sm = red[0];
    #pragma unroll
    for (int i = 0; i < 4; i++) {
        size_t o = base + tid + i * 256;
        split3(e[i] / sm, g_a0 + o, g_a1 + o, g_a2 + o);
    }
}

// ---------------- top-k selection ----------------
__global__ void sel_scan12() {
    int b = blockIdx.x, tid = threadIdx.x;
    __shared__ unsigned csum[256];
    unsigned s = 0;
    for (int k = 0; k < 16; k++) s += g_h12[b][tid * 16 + k];
    csum[tid] = s;
    __syncthreads();
    if (tid == 0) {
        unsigned acc = 0; int c = 255;
        for (; c >= 0; c--) { if (acc + csum[c] >= (unsigned)KSEL) break; acc += csum[c]; }
        int bin = c * 16 + 15;
        for (;; bin--) { unsigned ct = g_h12[b][bin]; if (acc + ct >= (unsigned)KSEL) break; acc += ct; }
        g_s3[b].P12 = (unsigned)bin;
        g_s3[b].kneed = (unsigned)KSEL - acc;
    }
}

__global__ void sel_gather12() {
    int b = blockIdx.y;
    unsigned P = g_s3[b].P12;
    const float4* W = (const float4*)(g_W + (size_t)b * SS);
    for (int i = blockIdx.x * blockDim.x + threadIdx.x; i < SS/4; i += gridDim.x * blockDim.x) {
        float4 v = W[i];
        unsigned base = i * 4;
        float vv[4] = {v.x, v.y, v.z, v.w};
        #pragma unroll
        for (int j = 0; j < 4; j++) {
            unsigned u = fkey(vv[j]);
            if ((u >> 20) == P) {
                unsigned pos = atomicAdd(&g_s3[b].ncand, 1u);
                g_cand[b][pos] = ((unsigned long long)u << 32) | (base + j);
            }
        }
    }
}

__global__ void sel_finish() {
    int b = blockIdx.x, tid = threadIdx.x;
    __shared__ unsigned h[256];
    __shared__ unsigned s_prefix, s_kneed;
    unsigned n = g_s3[b].ncand;
    if (tid == 0) { s_prefix = 0; s_kneed = g_s3[b].kneed; }
    __syncthreads();
    const int shs[3] = {12, 4, 0};
    const unsigned wids[3] = {256, 256, 16};
    #pragma unroll
    for (int lvl = 0; lvl < 3; lvl++) {
        int sh = shs[lvl];
        unsigned w = wids[lvl];
        unsigned pmask = (lvl == 0) ? 0u : (0xFFFFFu << (shs[lvl-1]));
        if (tid < w) h[tid] = 0;
        __syncthreads();
        unsigned pfx = s_prefix;
        for (unsigned i = tid; i < n; i += 1024) {
            unsigned low = ((unsigned)(g_cand[b][i] >> 32)) & 0xFFFFFu;
            if ((low & pmask) == pfx) atomicAdd(&h[(low >> sh) & (w - 1)], 1u);
        }
        __syncthreads();
        if (tid == 0) {
            unsigned kneed = s_kneed;
            int bin = (int)w - 1;
            for (; bin >= 0; bin--) { if (kneed <= h[bin]) break; kneed -= h[bin]; }
            s_prefix = pfx | ((unsigned)bin << sh);
            s_kneed = kneed;
        }
        __syncthreads();
    }
    unsigned T = (g_s3[b].P12 << 20) | s_prefix;
    if (tid == 0) s_prefix = 0;
    __syncthreads();
    #pragma unroll
    for (int lvl = 0; lvl < 3; lvl++) {
        int sh = shs[lvl];
        unsigned w = wids[lvl];
        unsigned pmask = (lvl == 0) ? 0u : (0xFFFFFu << (shs[lvl-1]));
        if (tid < w) h[tid] = 0;
        __syncthreads();
        unsigned pfx = s_prefix;
        for (unsigned i = tid; i < n; i += 1024) {
            unsigned long long cv = g_cand[b][i];
            unsigned key = (unsigned)(cv >> 32);
            unsigned idx = (unsigned)cv;
            if (key == T && (idx & pmask) == pfx) atomicAdd(&h[(idx >> sh) & (w - 1)], 1u);
        }
        __syncthreads();
        if (tid == 0) {
            unsigned kneed = s_kneed;
            int bin = (int)w - 1;
            for (; bin >= 0; bin--) { if (kneed <= h[bin]) break; kneed -= h[bin]; }
            s_prefix = pfx | ((unsigned)bin << sh);
            s_kneed = kneed;
        }
        __syncthreads();
    }
    if (tid == 0) { g_s3[b].T = T; g_s3[b].idxT = s_prefix; }
}

__global__ void mask_write(float* __restrict__ out) {
    int b = blockIdx.y;
    unsigned base = (blockIdx.x * 1024 + threadIdx.x) * 4;
    unsigned T = g_s3[b].T;
    unsigned idxT = g_s3[b].idxT;
    const float4 v = *(const float4*)(g_W + (size_t)b * SS + base);
    float r[4]; const float vv[4] = {v.x, v.y, v.z, v.w};
    #pragma unroll
    for (int j = 0; j < 4; j++) {
        unsigned u = fkey(vv[j]);
        r[j] = (u > T || (u == T && base + j >= idxT)) ? 1.0f : 0.0f;
    }
    *(float4*)(out + (size_t)b * SS + base) = make_float4(r[0], r[1], r[2], r[3]);
}

// ---------------- launcher ----------------
extern "C" void kernel_launch(void* const* d_in, const int* in_sizes, int n_in,
                              void* d_out, int out_size) {
    const float* x = (const float*)d_in[0];
    float* out = (float*)d_out;

    cudaFuncSetAttribute(gemm_mma, cudaFuncAttributeMaxDynamicSharedMemorySize, GSMEM);

    pairwise<<<dim3(528, 1, BATCH), 256>>>(x);
    gemm_mma<<<dim3(8, 8, BATCH), 512, GSMEM>>>(0);
    softmax_rows<<<dim3(NTOK, BATCH), 256>>>();
    gemm_mma<<<dim3(8, 8, BATCH), 512, GSMEM>>>(1);

    sel_scan12<<<BATCH, 256>>>();
    sel_gather12<<<dim3(128, BATCH), 256>>>();
    sel_finish<<<BATCH, 1024>>>();
    mask_write<<<dim3(SS / 4096, BATCH), 1024>>>(out);
}

// round 13
// speedup vs baseline: 1.0842x; 1.0842x over previous
#include <cuda_runtime.h>
#include <cuda_bf16.h>
#include <math.h>
#include <stdint.h>

#define NTOK 1024
#define CDIM 64
#define BATCH 2
#define SS (NTOK*NTOK)
#define KSEL (SS/6)   /* 174762 */

// ---------------- device scratch (no allocations allowed) ----------------
__device__ __nv_bfloat16 g_e0[BATCH*SS], g_e1[BATCH*SS], g_e2[BATCH*SS];
__device__ __nv_bfloat16 g_h0[BATCH*SS], g_h1[BATCH*SS], g_h2[BATCH*SS];
__device__ __nv_bfloat16 g_r0[BATCH*SS], g_r1[BATCH*SS], g_r2[BATCH*SS];
__device__ __nv_bfloat16 g_a0[BATCH*SS], g_a1[BATCH*SS], g_a2[BATCH*SS];
__device__ float g_L[BATCH*SS];
__device__ float g_W[BATCH*SS];
__device__ unsigned g_h12[BATCH][4096];
__device__ unsigned long long g_cand[BATCH][SS];
struct Sel3 { unsigned P12, kneed, T, idxT, ncand; };
__device__ Sel3 g_s3[BATCH];

__device__ __forceinline__ unsigned fkey(float f) {
    unsigned u = __float_as_uint(f);
    return (u & 0x80000000u) ? ~u : (u | 0x80000000u);
}

__device__ __forceinline__ void split3(float v, __nv_bfloat16* p0,
                                       __nv_bfloat16* p1, __nv_bfloat16* p2) {
    __nv_bfloat16 b0 = __float2bfloat16(v);
    float r = v - __bfloat162float(b0);
    __nv_bfloat16 b1 = __float2bfloat16(r);
    float r2 = r - __bfloat162float(b1);
    *p0 = b0; *p1 = b1; *p2 = __float2bfloat16(r2);
}

__device__ __forceinline__ uint32_t s2u(const void* p) {
    uint32_t a;
    asm("{ .reg .u64 t; cvta.to.shared.u64 t, %1; cvt.u32.u64 %0, t; }" : "=r"(a) : "l"(p));
    return a;
}

// ---------------- fused pairwise (upper triangle) -> bf16 splits ----------------
__global__ __launch_bounds__(256) void pairwise(const float* __restrict__ x) {
    __shared__ float xi[32][CDIM + 1];
    __shared__ float xj[32][CDIM + 1];
    __shared__ float smi[32], ssi[32], smj[32], ssj[32];
    __shared__ __nv_bfloat16 tb[9][32][36];
    int b = blockIdx.z;
    int t = blockIdx.x;
    int tid = threadIdx.x;

    if (b == 0 && t < 32) {
        int gid = t * 256 + tid;
        ((unsigned*)g_h12)[gid] = 0;
        if (gid < BATCH) g_s3[gid].ncand = 0;
    }

    int bi = (int)((65.0f - sqrtf(4225.0f - 8.0f * (float)t)) * 0.5f);
    while (32*bi - bi*(bi-1)/2 > t) bi--;
    while (32*(bi+1) - (bi+1)*bi/2 <= t) bi++;
    int bj = bi + (t - (32*bi - bi*(bi-1)/2));
    int i0 = bi * 32, j0 = bj * 32;

    const float* xb = x + (size_t)b * NTOK * CDIM;
    for (int l = tid; l < 32 * CDIM; l += 256) {
        int r = l >> 6, c = l & 63;
        xi[r][c] = xb[(size_t)(i0 + r) * CDIM + c];
        xj[r][c] = xb[(size_t)(j0 + r) * CDIM + c];
    }
    __syncthreads();

    {
        int warp = tid >> 5, lane = tid & 31;
        #pragma unroll
        for (int rr = 0; rr < 4; rr++) {
            int row = warp * 4 + rr;
            {
                float v0 = xi[row][lane], v1 = xi[row][lane + 32];
                float s = v0 + v1;
                #pragma unroll
                for (int o = 16; o; o >>= 1) s += __shfl_xor_sync(0xFFFFFFFFu, s, o);
                float mean = s * (1.0f / CDIM);
                float d0 = v0 - mean, d1 = v1 - mean;
                float ss = d0 * d0 + d1 * d1;
                #pragma unroll
                for (int o = 16; o; o >>= 1) ss += __shfl_xor_sync(0xFFFFFFFFu, ss, o);
                if (lane == 0) { smi[row] = mean; ssi[row] = sqrtf(ss); }
            }
            {
                float v0 = xj[row][lane], v1 = xj[row][lane + 32];
                float s = v0 + v1;
                #pragma unroll
                for (int o = 16; o; o >>= 1) s += __shfl_xor_sync(0xFFFFFFFFu, s, o);
                float mean = s * (1.0f / CDIM);
                float d0 = v0 - mean, d1 = v1 - mean;
                float ss = d0 * d0 + d1 * d1;
                #pragma unroll
                for (int o = 16; o; o >>= 1) ss += __shfl_xor_sync(0xFFFFFFFFu, ss, o);
                if (lane == 0) { smj[row] = mean; ssj[row] = sqrtf(ss); }
            }
        }
    }
    __syncthreads();

    int tx = tid & 15, ty = tid >> 4;
    int r0 = ty * 2, r1 = ty * 2 + 1;
    int c0 = tx, c1 = tx + 16;

    float ssq[2][2] = {{0,0},{0,0}};
    float mx[2][2]  = {{0,0},{0,0}};
    float dt[2][2]  = {{0,0},{0,0}};
    float mi0 = smi[r0], mi1 = smi[r1], mj0 = smj[c0], mj1 = smj[c1];

    #pragma unroll 16
    for (int c = 0; c < CDIM; c++) {
        float a0 = xi[r0][c], a1 = xi[r1][c];
        float b0 = xj[c0][c], b1 = xj[c1][c];
        float ac0 = a0 - mi0, ac1 = a1 - mi1;
        float bc0 = b0 - mj0, bc1 = b1 - mj1;
        float d;
        d = a0 - b0; ssq[0][0] = fmaf(d,d,ssq[0][0]); mx[0][0] = fmaxf(mx[0][0], fabsf(d)); dt[0][0] = fmaf(ac0,bc0,dt[0][0]);
        d = a0 - b1; ssq[0][1] = fmaf(d,d,ssq[0][1]); mx[0][1] = fmaxf(mx[0][1], fabsf(d)); dt[0][1] = fmaf(ac0,bc1,dt[0][1]);
        d = a1 - b0; ssq[1][0] = fmaf(d,d,ssq[1][0]); mx[1][0] = fmaxf(mx[1][0], fabsf(d)); dt[1][0] = fmaf(ac1,bc0,dt[1][0]);
        d = a1 - b1; ssq[1][1] = fmaf(d,d,ssq[1][1]); mx[1][1] = fmaxf(mx[1][1], fabsf(d)); dt[1][1] = fmaf(ac1,bc1,dt[1][1]);
    }

    size_t boff = (size_t)b * SS;
    __nv_bfloat16* Gm[9] = { g_e0+boff, g_e1+boff, g_e2+boff,
                             g_h0+boff, g_h1+boff, g_h2+boff,
                             g_r0+boff, g_r1+boff, g_r2+boff };
    __nv_bfloat16 sv[9][2][2];
    #pragma unroll
    for (int p = 0; p < 2; p++) {
        float si = ssi[r0 + p];
        #pragma unroll
        for (int q = 0; q < 2; q++) {
            split3(sqrtf(ssq[p][q]), &sv[0][p][q], &sv[1][p][q], &sv[2][p][q]);
            split3(mx[p][q],         &sv[3][p][q], &sv[4][p][q], &sv[5][p][q]);
            float cr = dt[p][q] / (si * ssj[(q==0)?c0:c1]);
            cr = fminf(fmaxf(cr, -1.0f), 1.0f);
            split3(cr, &sv[6][p][q], &sv[7][p][q], &sv[8][p][q]);
        }
    }

    #pragma unroll
    for (int m = 0; m < 9; m++) {
        #pragma unroll
        for (int p = 0; p < 2; p++) {
            #pragma unroll
            for (int q = 0; q < 2; q++) {
                int I = i0 + r0 + p;
                int J = j0 + ((q == 0) ? c0 : c1);
                Gm[m][(size_t)I * NTOK + J] = sv[m][p][q];
            }
        }
    }

    if (bi != bj) {
        #pragma unroll
        for (int m = 0; m < 9; m++) {
            tb[m][c0][r0] = sv[m][0][0];
            tb[m][c0][r1] = sv[m][1][0];
            tb[m][c1][r0] = sv[m][0][1];
            tb[m][c1][r1] = sv[m][1][1];
        }
        __syncthreads();
        int wr = tid >> 3, wc = (tid & 7) * 4;
        #pragma unroll
        for (int m = 0; m < 9; m++) {
            uint2 v = *(const uint2*)&tb[m][wr][wc];
            *(uint2*)(Gm[m] + (size_t)(j0 + wr) * NTOK + i0 + wc) = v;
        }
    }
}

// ---------------- bf16x6 GEMM via mma.sync (HMMA), 512 thr, KC=64, frag pipeline ----------------
#define KC 64
#define ROWB 144                /* 128B data + 16B pad */
#define TILEB (128*ROWB)        /* 18432 */
#define STAGEB (6*TILEB)        /* 110592 */
#define GSMEM (2*STAGEB)        /* 221184 */

#define LDSM4(r, a) \
    asm volatile("ldmatrix.sync.aligned.m8n8.x4.shared.b16 {%0,%1,%2,%3}, [%4];" \
        : "=r"((r)[0]), "=r"((r)[1]), "=r"((r)[2]), "=r"((r)[3]) : "r"(a))

#define MMA16816(d, a, b0r, b1r) \
    asm volatile("mma.sync.aligned.m16n8k16.row.col.f32.bf16.bf16.f32 " \
        "{%0,%1,%2,%3}, {%4,%5,%6,%7}, {%8,%9}, {%0,%1,%2,%3};" \
        : "+f"((d)[0]), "+f"((d)[1]), "+f"((d)[2]), "+f"((d)[3]) \
        : "r"((a)[0]), "r"((a)[1]), "r"((a)[2]), "r"((a)[3]), "r"(b0r), "r"(b1r))

__device__ __forceinline__ void load_frags(uint32_t stoff, unsigned aRowOff, unsigned bRowOff,
                                           int kf, uint32_t af[3][2][4], uint32_t bf[3][2][4]) {
    #pragma unroll
    for (int s = 0; s < 3; s++) {
        #pragma unroll
        for (int mf = 0; mf < 2; mf++)
            LDSM4(af[s][mf], stoff + s*TILEB + aRowOff + mf*(16*ROWB) + kf*32);
        #pragma unroll
        for (int np = 0; np < 2; np++)
            LDSM4(bf[s][np], stoff + (3+s)*TILEB + bRowOff + np*(16*ROWB) + kf*32);
    }
}

__global__ __launch_bounds__(512, 1) void gemm_mma(int which) {
    extern __shared__ __align__(128) char dsm[];
    uint32_t sb = s2u(dsm);
    int tid = threadIdx.x, lane = tid & 31, wid = tid >> 5;
    int wm = wid >> 2, wn = wid & 3;   // warp grid 4x4, warp tile 32x32
    size_t boff = (size_t)blockIdx.z * SS;
    const __nv_bfloat16* mats[6];
    if (which == 0) {
        mats[0]=g_e0+boff; mats[1]=g_e1+boff; mats[2]=g_e2+boff;
        mats[3]=g_h0+boff; mats[4]=g_h1+boff; mats[5]=g_h2+boff;
    } else {
        mats[0]=g_a0+boff; mats[1]=g_a1+boff; mats[2]=g_a2+boff;
        mats[3]=g_r0+boff; mats[4]=g_r1+boff; mats[5]=g_r2+boff;
    }
    float* C = (which == 0 ? g_L : g_W) + boff;
    int rowBase = blockIdx.y * 128, colBase = blockIdx.x * 128;

    float acc[2][4][4];
    #pragma unroll
    for (int i = 0; i < 2; i++)
        #pragma unroll
        for (int j = 0; j < 4; j++)
            #pragma unroll
            for (int k = 0; k < 4; k++) acc[i][j][k] = 0.0f;

    unsigned aRowOff = (unsigned)(wm*32 + (lane & 15)) * ROWB + ((lane >> 4) << 4);
    unsigned bRowOff = (unsigned)(wn*32 + (lane & 7) + ((lane >> 4) << 3)) * ROWB
                     + (((lane >> 3) & 1) << 4);

// 512 threads: per tile 128 rows x 8 chunks(16B) = 1024 chunks -> 2 per thread
#define LOADSTAGE(st, k0) do { \
    unsigned _so = sb + (unsigned)(st)*STAGEB; \
    _Pragma("unroll") \
    for (int i = 0; i < 6; i++) { \
        int rb = (i < 3) ? rowBase : colBase; \
        _Pragma("unroll") \
        for (int j = 0; j < 2; j++) { \
            int chunk = j * 512 + tid; \
            int row = chunk >> 3, c8 = chunk & 7; \
            const __nv_bfloat16* gp = mats[i] + (size_t)(rb + row) * NTOK + (k0) + c8*8; \
            unsigned sa = _so + i*TILEB + row*ROWB + c8*16; \
            asm volatile("cp.async.cg.shared.global [%0], [%1], 16;" :: "r"(sa), "l"(gp)); \
        } \
    } \
    asm volatile("cp.async.commit_group;"); \
} while(0)

    LOADSTAGE(0, 0);

    const int pa[6] = {0,0,1,0,1,2}, pb[6] = {0,1,0,2,1,0};

    for (int t = 0; t < 16; t++) {
        if (t < 15) {
            LOADSTAGE((t + 1) & 1, (t + 1) * KC);
            asm volatile("cp.async.wait_group 1;");
        } else {
            asm volatile("cp.async.wait_group 0;");
        }
        __syncthreads();
        unsigned stoff = sb + (unsigned)(t & 1) * STAGEB;

        uint32_t af[2][3][2][4];
        uint32_t bf[2][3][2][4];
        load_frags(stoff, aRowOff, bRowOff, 0, af[0], bf[0]);
        #pragma unroll
        for (int kf = 0; kf < 4; kf++) {
            int cur = kf & 1;
            if (kf < 3)
                load_frags(stoff, aRowOff, bRowOff, kf + 1, af[cur ^ 1], bf[cur ^ 1]);
            #pragma unroll
            for (int p = 0; p < 6; p++) {
                int sa = pa[p], sbp = pb[p];
                #pragma unroll
                for (int mf = 0; mf < 2; mf++) {
                    MMA16816(acc[mf][0], af[cur][sa][mf], bf[cur][sbp][0][0], bf[cur][sbp][0][1]);
                    MMA16816(acc[mf][1], af[cur][sa][mf], bf[cur][sbp][0][2], bf[cur][sbp][0][3]);
                    MMA16816(acc[mf][2], af[cur][sa][mf], bf[cur][sbp][1][0], bf[cur][sbp][1][1]);
                    MMA16816(acc[mf][3], af[cur][sa][mf], bf[cur][sbp][1][2], bf[cur][sbp][1][3]);
                }
            }
        }
        __syncthreads();
    }

    int r0 = rowBase + wm * 32 + (lane >> 2);
    int c0 = colBase + wn * 32 + (lane & 3) * 2;
    #pragma unroll
    for (int mf = 0; mf < 2; mf++) {
        #pragma unroll
        for (int nb = 0; nb < 4; nb++) {
            float* base = C + (size_t)(r0 + mf * 16) * NTOK + c0 + nb * 8;
            *(float2*)base = make_float2(acc[mf][nb][0], acc[mf][nb][1]);
            *(float2*)(base + 8 * NTOK) = make_float2(acc[mf][nb][2], acc[mf][nb][3]);
        }
    }

    // ---- fused selection histogram (gemm2 only) ----
    if (which == 1) {
        unsigned* hist = (unsigned*)dsm;
        __syncthreads();
        for (int i = tid; i < 4096; i += 512) hist[i] = 0;
        __syncthreads();
        #pragma unroll
        for (int mf = 0; mf < 2; mf++)
            #pragma unroll
            for (int nb = 0; nb < 4; nb++)
                #pragma unroll
                for (int k = 0; k < 4; k++)
                    atomicAdd(&hist[fkey(acc[mf][nb][k]) >> 20], 1u);
        __syncthreads();
        int b = blockIdx.z;
        for (int i = tid; i < 4096; i += 512)
            if (hist[i]) atomicAdd(&g_h12[b][i], hist[i]);
    }
#undef LOADSTAGE
}

// ---------------- row softmax of 0.125*L -> attn bf16 splits ----------------
__global__ void softmax_rows() {
    int b = blockIdx.y, row = blockIdx.x;
    size_t base = (size_t)b * SS + (size_t)row * NTOK;
    float* L = g_L + base;
    int tid = threadIdx.x;  // 256
    float v[4];
    #pragma unroll
    for (int i = 0; i < 4; i++) v[i] = L[tid + i * 256] * 0.125f;
    float m = fmaxf(fmaxf(v[0], v[1]), fmaxf(v[2], v[3]));
    __shared__ float red[256];
    red[tid] = m; __syncthreads();
    for (int s = 128; s; s >>= 1) { if (tid < s) red[tid] = fmaxf(red[tid], red[tid + s]); __syncthreads(); }
    m = red[0]; __syncthreads();
    float e[4], sm = 0.0f;
    #pragma unroll
    for (int i = 0; i < 4; i++) { e[i] = expf(v[i] - m); sm += e[i]; }
    red[tid] = sm; __syncthreads();
    for (int s = 128; s; s >>= 1) { if (tid < s) red[tid] += red[tid + s]; __syncthreads(); }
    sm = red[0];
    #pragma unroll
    for (int i = 0; i < 4; i++) {
        size_t o = base + tid + i * 256;
        split3(e[i] / sm, g_a0 + o, g_a1 + o, g_a2 + o);
    }
}

// ---------------- top-k selection ----------------
__global__ void sel_scan12() {
    int b = blockIdx.x, tid = threadIdx.x;
    __shared__ unsigned csum[256];
    unsigned s = 0;
    for (int k = 0; k < 16; k++) s += g_h12[b][tid * 16 + k];
    csum[tid] = s;
    __syncthreads();
    if (tid == 0) {
        unsigned acc = 0; int c = 255;
        for (; c >= 0; c--) { if (acc + csum[c] >= (unsigned)KSEL) break; acc += csum[c]; }
        int bin = c * 16 + 15;
        for (;; bin--) { unsigned ct = g_h12[b][bin]; if (acc + ct >= (unsigned)KSEL) break; acc += ct; }
        g_s3[b].P12 = (unsigned)bin;
        g_s3[b].kneed = (unsigned)KSEL - acc;
    }
}

__global__ void sel_gather12() {
    int b = blockIdx.y;
    unsigned P = g_s3[b].P12;
    const float4* W = (const float4*)(g_W + (size_t)b * SS);
    for (int i = blockIdx.x * blockDim.x + threadIdx.x; i < SS/4; i += gridDim.x * blockDim.x) {
        float4 v = W[i];
        unsigned base = i * 4;
        float vv[4] = {v.x, v.y, v.z, v.w};
        #pragma unroll
        for (int j = 0; j < 4; j++) {
            unsigned u = fkey(vv[j]);
            if ((u >> 20) == P) {
                unsigned pos = atomicAdd(&g_s3[b].ncand, 1u);
                g_cand[b][pos] = ((unsigned long long)u << 32) | (base + j);
            }
        }
    }
}

__global__ void sel_finish() {
    int b = blockIdx.x, tid = threadIdx.x;
    __shared__ unsigned h[256];
    __shared__ unsigned s_prefix, s_kneed;
    unsigned n = g_s3[b].ncand;
    if (tid == 0) { s_prefix = 0; s_kneed = g_s3[b].kneed; }
    __syncthreads();
    const int shs[3] = {12, 4, 0};
    const unsigned wids[3] = {256, 256, 16};
    #pragma unroll
    for (int lvl = 0; lvl < 3; lvl++) {
        int sh = shs[lvl];
        unsigned w = wids[lvl];
        unsigned pmask = (lvl == 0) ? 0u : (0xFFFFFu << (shs[lvl-1]));
        if (tid < w) h[tid] = 0;
        __syncthreads();
        unsigned pfx = s_prefix;
        for (unsigned i = tid; i < n; i += 1024) {
            unsigned low = ((unsigned)(g_cand[b][i] >> 32)) & 0xFFFFFu;
            if ((low & pmask) == pfx) atomicAdd(&h[(low >> sh) & (w - 1)], 1u);
        }
        __syncthreads();
        if (tid == 0) {
            unsigned kneed = s_kneed;
            int bin = (int)w - 1;
            for (; bin >= 0; bin--) { if (kneed <= h[bin]) break; kneed -= h[bin]; }
            s_prefix = pfx | ((unsigned)bin << sh);
            s_kneed = kneed;
        }
        __syncthreads();
    }
    unsigned T = (g_s3[b].P12 << 20) | s_prefix;
    if (tid == 0) s_prefix = 0;
    __syncthreads();
    #pragma unroll
    for (int lvl = 0; lvl < 3; lvl++) {
        int sh = shs[lvl];
        unsigned w = wids[lvl];
        unsigned pmask = (lvl == 0) ? 0u : (0xFFFFFu << (shs[lvl-1]));
        if (tid < w) h[tid] = 0;
        __syncthreads();
        unsigned pfx = s_prefix;
        for (unsigned i = tid; i < n; i += 1024) {
            unsigned long long cv = g_cand[b][i];
            unsigned key = (unsigned)(cv >> 32);
            unsigned idx = (unsigned)cv;
            if (key == T && (idx & pmask) == pfx) atomicAdd(&h[(idx >> sh) & (w - 1)], 1u);
        }
        __syncthreads();
        if (tid == 0) {
            unsigned kneed = s_kneed;
            int bin = (int)w - 1;
            for (; bin >= 0; bin--) { if (kneed <= h[bin]) break; kneed -= h[bin]; }
            s_prefix = pfx | ((unsigned)bin << sh);
            s_kneed = kneed;
        }
        __syncthreads();
    }
    if (tid == 0) { g_s3[b].T = T; g_s3[b].idxT = s_prefix; }
}

__global__ void mask_write(float* __restrict__ out) {
    int b = blockIdx.y;
    unsigned base = (blockIdx.x * 1024 + threadIdx.x) * 4;
    unsigned T = g_s3[b].T;
    unsigned idxT = g_s3[b].idxT;
    const float4 v = *(const float4*)(g_W + (size_t)b * SS + base);
    float r[4]; const float vv[4] = {v.x, v.y, v.z, v.w};
    #pragma unroll
    for (int j = 0; j < 4; j++) {
        unsigned u = fkey(vv[j]);
        r[j] = (u > T || (u == T && base + j >= idxT)) ? 1.0f : 0.0f;
    }
    *(float4*)(out + (size_t)b * SS + base) = make_float4(r[0], r[1], r[2], r[3]);
}

// ---------------- launcher ----------------
extern "C" void kernel_launch(void* const* d_in, const int* in_sizes, int n_in,
                              void* d_out, int out_size) {
    const float* x = (const float*)d_in[0];
    float* out = (float*)d_out;

    cudaFuncSetAttribute(gemm_mma, cudaFuncAttributeMaxDynamicSharedMemorySize, GSMEM);

    pairwise<<<dim3(528, 1, BATCH), 256>>>(x);
    gemm_mma<<<dim3(8, 8, BATCH), 512, GSMEM>>>(0);
    softmax_rows<<<dim3(NTOK, BATCH), 256>>>();
    gemm_mma<<<dim3(8, 8, BATCH), 512, GSMEM>>>(1);

    sel_scan12<<<BATCH, 256>>>();
    sel_gather12<<<dim3(128, BATCH), 256>>>();
    sel_finish<<<BATCH, 1024>>>();
    mask_write<<<dim3(SS / 4096, BATCH), 1024>>>(out);
}

// round 14
// speedup vs baseline: 1.1275x; 1.0399x over previous
#include <cuda_runtime.h>
#include <cuda_bf16.h>
#include <math.h>
#include <stdint.h>

#define NTOK 1024
#define CDIM 64
#define BATCH 2
#define SS (NTOK*NTOK)
#define KSEL (SS/6)   /* 174762 */

// ---------------- device scratch (no allocations allowed) ----------------
__device__ __nv_bfloat16 g_e0[BATCH*SS], g_e1[BATCH*SS], g_e2[BATCH*SS];
__device__ __nv_bfloat16 g_h0[BATCH*SS], g_h1[BATCH*SS], g_h2[BATCH*SS];
__device__ __nv_bfloat16 g_r0[BATCH*SS], g_r1[BATCH*SS], g_r2[BATCH*SS];
__device__ __nv_bfloat16 g_a0[BATCH*SS], g_a1[BATCH*SS], g_a2[BATCH*SS];
__device__ float g_L[BATCH*SS];
__device__ float g_W[BATCH*SS];
__device__ unsigned g_h12[BATCH][4096];
__device__ unsigned long long g_cand[BATCH][SS];
struct Sel3 { unsigned P12, kneed, T, idxT, ncand; };
__device__ Sel3 g_s3[BATCH];

__device__ __forceinline__ unsigned fkey(float f) {
    unsigned u = __float_as_uint(f);
    return (u & 0x80000000u) ? ~u : (u | 0x80000000u);
}

__device__ __forceinline__ void split3(float v, __nv_bfloat16* p0,
                                       __nv_bfloat16* p1, __nv_bfloat16* p2) {
    __nv_bfloat16 b0 = __float2bfloat16(v);
    float r = v - __bfloat162float(b0);
    __nv_bfloat16 b1 = __float2bfloat16(r);
    float r2 = r - __bfloat162float(b1);
    *p0 = b0; *p1 = b1; *p2 = __float2bfloat16(r2);
}

__device__ __forceinline__ uint32_t s2u(const void* p) {
    uint32_t a;
    asm("{ .reg .u64 t; cvta.to.shared.u64 t, %1; cvt.u32.u64 %0, t; }" : "=r"(a) : "l"(p));
    return a;
}

// ---------------- fused pairwise (upper triangle) -> bf16 splits ----------------
__global__ __launch_bounds__(256) void pairwise(const float* __restrict__ x) {
    __shared__ float xi[32][CDIM + 1];
    __shared__ float xj[32][CDIM + 1];
    __shared__ float smi[32], ssi[32], smj[32], ssj[32];
    __shared__ __nv_bfloat16 tb[9][32][36];
    int b = blockIdx.z;
    int t = blockIdx.x;
    int tid = threadIdx.x;

    if (b == 0 && t < 32) {
        int gid = t * 256 + tid;
        ((unsigned*)g_h12)[gid] = 0;
        if (gid < BATCH) g_s3[gid].ncand = 0;
    }

    int bi = (int)((65.0f - sqrtf(4225.0f - 8.0f * (float)t)) * 0.5f);
    while (32*bi - bi*(bi-1)/2 > t) bi--;
    while (32*(bi+1) - (bi+1)*bi/2 <= t) bi++;
    int bj = bi + (t - (32*bi - bi*(bi-1)/2));
    int i0 = bi * 32, j0 = bj * 32;

    const float* xb = x + (size_t)b * NTOK * CDIM;
    for (int l = tid; l < 32 * CDIM; l += 256) {
        int r = l >> 6, c = l & 63;
        xi[r][c] = xb[(size_t)(i0 + r) * CDIM + c];
        xj[r][c] = xb[(size_t)(j0 + r) * CDIM + c];
    }
    __syncthreads();

    {
        int warp = tid >> 5, lane = tid & 31;
        #pragma unroll
        for (int rr = 0; rr < 4; rr++) {
            int row = warp * 4 + rr;
            {
                float v0 = xi[row][lane], v1 = xi[row][lane + 32];
                float s = v0 + v1;
                #pragma unroll
                for (int o = 16; o; o >>= 1) s += __shfl_xor_sync(0xFFFFFFFFu, s, o);
                float mean = s * (1.0f / CDIM);
                float d0 = v0 - mean, d1 = v1 - mean;
                float ss = d0 * d0 + d1 * d1;
                #pragma unroll
                for (int o = 16; o; o >>= 1) ss += __shfl_xor_sync(0xFFFFFFFFu, ss, o);
                if (lane == 0) { smi[row] = mean; ssi[row] = sqrtf(ss); }
            }
            {
                float v0 = xj[row][lane], v1 = xj[row][lane + 32];
                float s = v0 + v1;
                #pragma unroll
                for (int o = 16; o; o >>= 1) s += __shfl_xor_sync(0xFFFFFFFFu, s, o);
                float mean = s * (1.0f / CDIM);
                float d0 = v0 - mean, d1 = v1 - mean;
                float ss = d0 * d0 + d1 * d1;
                #pragma unroll
                for (int o = 16; o; o >>= 1) ss += __shfl_xor_sync(0xFFFFFFFFu, ss, o);
                if (lane == 0) { smj[row] = mean; ssj[row] = sqrtf(ss); }
            }
        }
    }
    __syncthreads();

    int tx = tid & 15, ty = tid >> 4;
    int r0 = ty * 2, r1 = ty * 2 + 1;
    int c0 = tx, c1 = tx + 16;

    float ssq[2][2] = {{0,0},{0,0}};
    float mx[2][2]  = {{0,0},{0,0}};
    float dt[2][2]  = {{0,0},{0,0}};
    float mi0 = smi[r0], mi1 = smi[r1], mj0 = smj[c0], mj1 = smj[c1];

    #pragma unroll 16
    for (int c = 0; c < CDIM; c++) {
        float a0 = xi[r0][c], a1 = xi[r1][c];
        float b0 = xj[c0][c], b1 = xj[c1][c];
        float ac0 = a0 - mi0, ac1 = a1 - mi1;
        float bc0 = b0 - mj0, bc1 = b1 - mj1;
        float d;
        d = a0 - b0; ssq[0][0] = fmaf(d,d,ssq[0][0]); mx[0][0] = fmaxf(mx[0][0], fabsf(d)); dt[0][0] = fmaf(ac0,bc0,dt[0][0]);
        d = a0 - b1; ssq[0][1] = fmaf(d,d,ssq[0][1]); mx[0][1] = fmaxf(mx[0][1], fabsf(d)); dt[0][1] = fmaf(ac0,bc1,dt[0][1]);
        d = a1 - b0; ssq[1][0] = fmaf(d,d,ssq[1][0]); mx[1][0] = fmaxf(mx[1][0], fabsf(d)); dt[1][0] = fmaf(ac1,bc0,dt[1][0]);
        d = a1 - b1; ssq[1][1] = fmaf(d,d,ssq[1][1]); mx[1][1] = fmaxf(mx[1][1], fabsf(d)); dt[1][1] = fmaf(ac1,bc1,dt[1][1]);
    }

    size_t boff = (size_t)b * SS;
    __nv_bfloat16* Gm[9] = { g_e0+boff, g_e1+boff, g_e2+boff,
                             g_h0+boff, g_h1+boff, g_h2+boff,
                             g_r0+boff, g_r1+boff, g_r2+boff };
    __nv_bfloat16 sv[9][2][2];
    #pragma unroll
    for (int p = 0; p < 2; p++) {
        float si = ssi[r0 + p];
        #pragma unroll
        for (int q = 0; q < 2; q++) {
            split3(sqrtf(ssq[p][q]), &sv[0][p][q], &sv[1][p][q], &sv[2][p][q]);
            split3(mx[p][q],         &sv[3][p][q], &sv[4][p][q], &sv[5][p][q]);
            float cr = dt[p][q] / (si * ssj[(q==0)?c0:c1]);
            cr = fminf(fmaxf(cr, -1.0f), 1.0f);
            split3(cr, &sv[6][p][q], &sv[7][p][q], &sv[8][p][q]);
        }
    }

    #pragma unroll
    for (int m = 0; m < 9; m++) {
        #pragma unroll
        for (int p = 0; p < 2; p++) {
            #pragma unroll
            for (int q = 0; q < 2; q++) {
                int I = i0 + r0 + p;
                int J = j0 + ((q == 0) ? c0 : c1);
                Gm[m][(size_t)I * NTOK + J] = sv[m][p][q];
            }
        }
    }

    if (bi != bj) {
        #pragma unroll
        for (int m = 0; m < 9; m++) {
            tb[m][c0][r0] = sv[m][0][0];
            tb[m][c0][r1] = sv[m][1][0];
            tb[m][c1][r0] = sv[m][0][1];
            tb[m][c1][r1] = sv[m][1][1];
        }
        __syncthreads();
        int wr = tid >> 3, wc = (tid & 7) * 4;
        #pragma unroll
        for (int m = 0; m < 9; m++) {
            uint2 v = *(const uint2*)&tb[m][wr][wc];
            *(uint2*)(Gm[m] + (size_t)(j0 + wr) * NTOK + i0 + wc) = v;
        }
    }
}

// ---- bf16x6 GEMM via mma.sync, 256 thr (255-reg budget), KC=64, interleaved frag pipeline ----
#define KC 64
#define ROWB 144                /* 128B data + 16B pad */
#define TILEB (128*ROWB)        /* 18432 */
#define STAGEB (6*TILEB)        /* 110592 */
#define GSMEM (2*STAGEB)        /* 221184 */

#define LDSM4(r, a) \
    asm volatile("ldmatrix.sync.aligned.m8n8.x4.shared.b16 {%0,%1,%2,%3}, [%4];" \
        : "=r"((r)[0]), "=r"((r)[1]), "=r"((r)[2]), "=r"((r)[3]) : "r"(a))

#define MMA16816(d, a, b0r, b1r) \
    asm volatile("mma.sync.aligned.m16n8k16.row.col.f32.bf16.bf16.f32 " \
        "{%0,%1,%2,%3}, {%4,%5,%6,%7}, {%8,%9}, {%0,%1,%2,%3};" \
        : "+f"((d)[0]), "+f"((d)[1]), "+f"((d)[2]), "+f"((d)[3]) \
        : "r"((a)[0]), "r"((a)[1]), "r"((a)[2]), "r"((a)[3]), "r"(b0r), "r"(b1r))

// load LDSM group g (0..17) of k-fragment kf into (af, bf)
// g 0..11 -> af[g>>2][g&3]; g 12..17 -> bf[(g-12)>>1][(g-12)&1]
#define LOAD_GROUP(g, kf, af, bf) do { \
    if ((g) < 12) \
        LDSM4(af[(g) >> 2][(g) & 3], \
              stoff + ((g) >> 2)*TILEB + aRowOff + ((g) & 3)*(16*ROWB) + (kf)*32); \
    else \
        LDSM4(bf[((g) - 12) >> 1][((g) - 12) & 1], \
              stoff + (3 + (((g) - 12) >> 1))*TILEB + bRowOff + (((g) - 12) & 1)*(16*ROWB) + (kf)*32); \
} while(0)

__global__ __launch_bounds__(256, 1) void gemm_mma(int which) {
    extern __shared__ __align__(128) char dsm[];
    uint32_t sb = s2u(dsm);
    int tid = threadIdx.x, lane = tid & 31, wid = tid >> 5;
    int wm = wid >> 2, wn = wid & 3;   // warp grid 2x4, warp tile 64x32
    size_t boff = (size_t)blockIdx.z * SS;
    const __nv_bfloat16* mats[6];
    if (which == 0) {
        mats[0]=g_e0+boff; mats[1]=g_e1+boff; mats[2]=g_e2+boff;
        mats[3]=g_h0+boff; mats[4]=g_h1+boff; mats[5]=g_h2+boff;
    } else {
        mats[0]=g_a0+boff; mats[1]=g_a1+boff; mats[2]=g_a2+boff;
        mats[3]=g_r0+boff; mats[4]=g_r1+boff; mats[5]=g_r2+boff;
    }
    float* C = (which == 0 ? g_L : g_W) + boff;
    int rowBase = blockIdx.y * 128, colBase = blockIdx.x * 128;

    float acc[4][4][4];
    #pragma unroll
    for (int i = 0; i < 4; i++)
        #pragma unroll
        for (int j = 0; j < 4; j++)
            #pragma unroll
            for (int k = 0; k < 4; k++) acc[i][j][k] = 0.0f;

    unsigned aRowOff = (unsigned)(wm*64 + (lane & 15)) * ROWB + ((lane >> 4) << 4);
    unsigned bRowOff = (unsigned)(wn*32 + (lane & 7) + ((lane >> 4) << 3)) * ROWB
                     + (((lane >> 3) & 1) << 4);

// 256 threads: per tile 1024 chunks(16B) -> 4 per thread
#define LOADSTAGE(st, k0) do { \
    unsigned _so = sb + (unsigned)(st)*STAGEB; \
    _Pragma("unroll") \
    for (int i = 0; i < 6; i++) { \
        int rb = (i < 3) ? rowBase : colBase; \
        _Pragma("unroll") \
        for (int j = 0; j < 4; j++) { \
            int chunk = j * 256 + tid; \
            int row = chunk >> 3, c8 = chunk & 7; \
            const __nv_bfloat16* gp = mats[i] + (size_t)(rb + row) * NTOK + (k0) + c8*8; \
            unsigned sa = _so + i*TILEB + row*ROWB + c8*16; \
            asm volatile("cp.async.cg.shared.global [%0], [%1], 16;" :: "r"(sa), "l"(gp)); \
        } \
    } \
    asm volatile("cp.async.commit_group;"); \
} while(0)

    LOADSTAGE(0, 0);

    const int pa[6] = {0,0,1,0,1,2}, pb[6] = {0,1,0,2,1,0};

    for (int t = 0; t < 16; t++) {
        if (t < 15) {
            LOADSTAGE((t + 1) & 1, (t + 1) * KC);
            asm volatile("cp.async.wait_group 1;");
        } else {
            asm volatile("cp.async.wait_group 0;");
        }
        __syncthreads();
        unsigned stoff = sb + (unsigned)(t & 1) * STAGEB;

        uint32_t af[2][3][4][4];
        uint32_t bf[2][3][2][4];
        // prologue: load kf=0 fragments
        #pragma unroll
        for (int g = 0; g < 18; g++) LOAD_GROUP(g, 0, af[0], bf[0]);
        #pragma unroll
        for (int kf = 0; kf < 4; kf++) {
            int cur = kf & 1, nxt = cur ^ 1;
            #pragma unroll
            for (int p = 0; p < 6; p++) {
                // interleave 3 next-kf LDSM groups before each product group
                if (kf < 3) {
                    #pragma unroll
                    for (int g = p * 3; g < p * 3 + 3; g++)
                        LOAD_GROUP(g, kf + 1, af[nxt], bf[nxt]);
                }
                int sa = pa[p], sbp = pb[p];
                #pragma unroll
                for (int mf = 0; mf < 4; mf++) {
                    MMA16816(acc[mf][0], af[cur][sa][mf], bf[cur][sbp][0][0], bf[cur][sbp][0][1]);
                    MMA16816(acc[mf][1], af[cur][sa][mf], bf[cur][sbp][0][2], bf[cur][sbp][0][3]);
                    MMA16816(acc[mf][2], af[cur][sa][mf], bf[cur][sbp][1][0], bf[cur][sbp][1][1]);
                    MMA16816(acc[mf][3], af[cur][sa][mf], bf[cur][sbp][1][2], bf[cur][sbp][1][3]);
                }
            }
        }
        __syncthreads();
    }

    int r0 = rowBase + wm * 64 + (lane >> 2);
    int c0 = colBase + wn * 32 + (lane & 3) * 2;
    #pragma unroll
    for (int mf = 0; mf < 4; mf++) {
        #pragma unroll
        for (int nb = 0; nb < 4; nb++) {
            float* base = C + (size_t)(r0 + mf * 16) * NTOK + c0 + nb * 8;
            *(float2*)base = make_float2(acc[mf][nb][0], acc[mf][nb][1]);
            *(float2*)(base + 8 * NTOK) = make_float2(acc[mf][nb][2], acc[mf][nb][3]);
        }
    }

    // ---- fused selection histogram (gemm2 only): 64 acc values x 256 threads ----
    if (which == 1) {
        unsigned* hist = (unsigned*)dsm;
        __syncthreads();
        for (int i = tid; i < 4096; i += 256) hist[i] = 0;
        __syncthreads();
        #pragma unroll
        for (int mf = 0; mf < 4; mf++)
            #pragma unroll
            for (int nb = 0; nb < 4; nb++)
                #pragma unroll
                for (int k = 0; k < 4; k++)
                    atomicAdd(&hist[fkey(acc[mf][nb][k]) >> 20], 1u);
        __syncthreads();
        int b = blockIdx.z;
        for (int i = tid; i < 4096; i += 256)
            if (hist[i]) atomicAdd(&g_h12[b][i], hist[i]);
    }
#undef LOADSTAGE
}

// ---------------- row softmax of 0.125*L -> attn bf16 splits ----------------
__global__ void softmax_rows() {
    int b = blockIdx.y, row = blockIdx.x;
    size_t base = (size_t)b * SS + (size_t)row * NTOK;
    float* L = g_L + base;
    int tid = threadIdx.x;  // 256
    float v[4];
    #pragma unroll
    for (int i = 0; i < 4; i++) v[i] = L[tid + i * 256] * 0.125f;
    float m = fmaxf(fmaxf(v[0], v[1]), fmaxf(v[2], v[3]));
    __shared__ float red[256];
    red[tid] = m; __syncthreads();
    for (int s = 128; s; s >>= 1) { if (tid < s) red[tid] = fmaxf(red[tid], red[tid + s]); __syncthreads(); }
    m = red[0]; __syncthreads();
    float e[4], sm = 0.0f;
    #pragma unroll
    for (int i = 0; i < 4; i++) { e[i] = expf(v[i] - m); sm += e[i]; }
    red[tid] = sm; __syncthreads();
    for (int s = 128; s; s >>= 1) { if (tid < s) red[tid] += red[tid + s]; __syncthreads(); }
    sm = red[0];
    #pragma unroll
    for (int i = 0; i < 4; i++) {
        size_t o = base + tid + i * 256;
        split3(e[i] / sm, g_a0 + o, g_a1 + o, g_a2 + o);
    }
}

// ---------------- top-k selection ----------------
__global__ void sel_scan12() {
    int b = blockIdx.x, tid = threadIdx.x;
    __shared__ unsigned csum[256];
    unsigned s = 0;
    for (int k = 0; k < 16; k++) s += g_h12[b][tid * 16 + k];
    csum[tid] = s;
    __syncthreads();
    if (tid == 0) {
        unsigned acc = 0; int c = 255;
        for (; c >= 0; c--) { if (acc + csum[c] >= (unsigned)KSEL) break; acc += csum[c]; }
        int bin = c * 16 + 15;
        for (;; bin--) { unsigned ct = g_h12[b][bin]; if (acc + ct >= (unsigned)KSEL) break; acc += ct; }
        g_s3[b].P12 = (unsigned)bin;
        g_s3[b].kneed = (unsigned)KSEL - acc;
    }
}

__global__ void sel_gather12() {
    int b = blockIdx.y;
    unsigned P = g_s3[b].P12;
    const float4* W = (const float4*)(g_W + (size_t)b * SS);
    for (int i = blockIdx.x * blockDim.x + threadIdx.x; i < SS/4; i += gridDim.x * blockDim.x) {
        float4 v = W[i];
        unsigned base = i * 4;
        float vv[4] = {v.x, v.y, v.z, v.w};
        #pragma unroll
        for (int j = 0; j < 4; j++) {
            unsigned u = fkey(vv[j]);
            if ((u >> 20) == P) {
                unsigned pos = atomicAdd(&g_s3[b].ncand, 1u);
                g_cand[b][pos] = ((unsigned long long)u << 32) | (base + j);
            }
        }
    }
}

__global__ void sel_finish() {
    int b = blockIdx.x, tid = threadIdx.x;
    __shared__ unsigned h[256];
    __shared__ unsigned s_prefix, s_kneed;
    unsigned n = g_s3[b].ncand;
    if (tid == 0) { s_prefix = 0; s_kneed = g_s3[b].kneed; }
    __syncthreads();
    const int shs[3] = {12, 4, 0};
    const unsigned wids[3] = {256, 256, 16};
    #pragma unroll
    for (int lvl = 0; lvl < 3; lvl++) {
        int sh = shs[lvl];
        unsigned w = wids[lvl];
        unsigned pmask = (lvl == 0) ? 0u : (0xFFFFFu << (shs[lvl-1]));
        if (tid < w) h[tid] = 0;
        __syncthreads();
        unsigned pfx = s_prefix;
        for (unsigned i = tid; i < n; i += 1024) {
            unsigned low = ((unsigned)(g_cand[b][i] >> 32)) & 0xFFFFFu;
            if ((low & pmask) == pfx) atomicAdd(&h[(low >> sh) & (w - 1)], 1u);
        }
        __syncthreads();
        if (tid == 0) {
            unsigned kneed = s_kneed;
            int bin = (int)w - 1;
            for (; bin >= 0; bin--) { if (kneed <= h[bin]) break; kneed -= h[bin]; }
            s_prefix = pfx | ((unsigned)bin << sh);
            s_kneed = kneed;
        }
        __syncthreads();
    }
    unsigned T = (g_s3[b].P12 << 20) | s_prefix;
    if (tid == 0) s_prefix = 0;
    __syncthreads();
    #pragma unroll
    for (int lvl = 0; lvl < 3; lvl++) {
        int sh = shs[lvl];
        unsigned w = wids[lvl];
        unsigned pmask = (lvl == 0) ? 0u : (0xFFFFFu << (shs[lvl-1]));
        if (tid < w) h[tid] = 0;
        __syncthreads();
        unsigned pfx = s_prefix;
        for (unsigned i = tid; i < n; i += 1024) {
            unsigned long long cv = g_cand[b][i];
            unsigned key = (unsigned)(cv >> 32);
            unsigned idx = (unsigned)cv;
            if (key == T && (idx & pmask) == pfx) atomicAdd(&h[(idx >> sh) & (w - 1)], 1u);
        }
        __syncthreads();
        if (tid == 0) {
            unsigned kneed = s_kneed;
            int bin = (int)w - 1;
            for (; bin >= 0; bin--) { if (kneed <= h[bin]) break; kneed -= h[bin]; }
            s_prefix = pfx | ((unsigned)bin << sh);
            s_kneed = kneed;
        }
        __syncthreads();
    }
    if (tid == 0) { g_s3[b].T = T; g_s3[b].idxT = s_prefix; }
}

__global__ void mask_write(float* __restrict__ out) {
    int b = blockIdx.y;
    unsigned base = (blockIdx.x * 1024 + threadIdx.x) * 4;
    unsigned T = g_s3[b].T;
    unsigned idxT = g_s3[b].idxT;
    const float4 v = *(const float4*)(g_W + (size_t)b * SS + base);
    float r[4]; const float vv[4] = {v.x, v.y, v.z, v.w};
    #pragma unroll
    for (int j = 0; j < 4; j++) {
        unsigned u = fkey(vv[j]);
        r[j] = (u > T || (u == T && base + j >= idxT)) ? 1.0f : 0.0f;
    }
    *(float4*)(out + (size_t)b * SS + base) = make_float4(r[0], r[1], r[2], r[3]);
}

// ---------------- launcher ----------------
extern "C" void kernel_launch(void* const* d_in, const int* in_sizes, int n_in,
                              void* d_out, int out_size) {
    const float* x = (const float*)d_in[0];
    float* out = (float*)d_out;

    cudaFuncSetAttribute(gemm_mma, cudaFuncAttributeMaxDynamicSharedMemorySize, GSMEM);

    pairwise<<<dim3(528, 1, BATCH), 256>>>(x);
    gemm_mma<<<dim3(8, 8, BATCH), 256, GSMEM>>>(0);
    softmax_rows<<<dim3(NTOK, BATCH), 256>>>();
    gemm_mma<<<dim3(8, 8, BATCH), 256, GSMEM>>>(1);

    sel_scan12<<<BATCH, 256>>>();
    sel_gather12<<<dim3(128, BATCH), 256>>>();
    sel_finish<<<BATCH, 1024>>>();
    mask_write<<<dim3(SS / 4096, BATCH), 1024>>>(out);
}